// round 15
// baseline (speedup 1.0000x reference)
#include <cuda_runtime.h>
#include <cuda_bf16.h>
#include <cuda_fp16.h>
#include <cstdint>

// Problem constants
#define SEQ   2048
#define BATCH 2
#define DM    1024
#define NH    16
#define DH    64
#define MTOK  (SEQ*BATCH)   // 4096 token rows

// ---------------- scratch (device globals) --------------------------------
__device__ __nv_bfloat16 g_db [MTOK * DM];              // dec, bf16 rn
__device__ __nv_bfloat16 g_wqb[DM * DM];
__device__ __nv_bfloat16 g_wkvb[2 * DM * DM];
__device__ __nv_bfloat16 g_wob[DM * DM];
__device__ __nv_bfloat16 g_wffh[DM * DM], g_wffl[DM * DM];
__device__ __nv_bfloat16 g_qb [MTOK * DM];
__device__ __nv_bfloat16 g_kvb[MTOK * 2 * DM];          // [token][K(bf16)|V(fp16)]
__device__ __nv_bfloat16 g_vecb[MTOK * DM];
__device__ __nv_bfloat16 g_h1h[MTOK * DM], g_h1l[MTOK * DM];
__device__ float g_h0[MTOK * DM];
__device__ float g_f0[MTOK * DM];

// ===================== common helpers ======================================
__device__ __forceinline__ void ldsm_x4(uint32_t r[4], uint32_t addr) {
    asm volatile("ldmatrix.sync.aligned.m8n8.x4.shared.b16 {%0,%1,%2,%3}, [%4];\n"
                 : "=r"(r[0]), "=r"(r[1]), "=r"(r[2]), "=r"(r[3]) : "r"(addr));
}
__device__ __forceinline__ void ldsm_x4_t(uint32_t r[4], uint32_t addr) {
    asm volatile("ldmatrix.sync.aligned.m8n8.x4.trans.shared.b16 {%0,%1,%2,%3}, [%4];\n"
                 : "=r"(r[0]), "=r"(r[1]), "=r"(r[2]), "=r"(r[3]) : "r"(addr));
}

__device__ __forceinline__ void mma16816(float c[4],
                                         uint32_t a0, uint32_t a1, uint32_t a2, uint32_t a3,
                                         uint32_t b0, uint32_t b1) {
    asm volatile(
        "mma.sync.aligned.m16n8k16.row.col.f32.bf16.bf16.f32 "
        "{%0,%1,%2,%3}, {%4,%5,%6,%7}, {%8,%9}, {%0,%1,%2,%3};\n"
        : "+f"(c[0]), "+f"(c[1]), "+f"(c[2]), "+f"(c[3])
        : "r"(a0), "r"(a1), "r"(a2), "r"(a3), "r"(b0), "r"(b1));
}
__device__ __forceinline__ void mma16816h(float c[4],
                                          uint32_t a0, uint32_t a1, uint32_t a2, uint32_t a3,
                                          uint32_t b0, uint32_t b1) {
    asm volatile(
        "mma.sync.aligned.m16n8k16.row.col.f32.f16.f16.f32 "
        "{%0,%1,%2,%3}, {%4,%5,%6,%7}, {%8,%9}, {%0,%1,%2,%3};\n"
        : "+f"(c[0]), "+f"(c[1]), "+f"(c[2]), "+f"(c[3])
        : "r"(a0), "r"(a1), "r"(a2), "r"(a3), "r"(b0), "r"(b1));
}

__device__ __forceinline__ void cp16(uint32_t dst, const void* src) {
    asm volatile("cp.async.cg.shared.global [%0], [%1], 16;\n" :: "r"(dst), "l"(src));
}
#define CP_COMMIT()  asm volatile("cp.async.commit_group;\n")
#define CP_WAIT(n)   asm volatile("cp.async.wait_group %0;\n" :: "n"(n))

__device__ __forceinline__ void split4(float4 v, uint32_t hp[2], uint32_t lp[2]) {
    uint32_t u0 = __float_as_uint(v.x), u1 = __float_as_uint(v.y);
    uint32_t u2 = __float_as_uint(v.z), u3 = __float_as_uint(v.w);
    hp[0] = __byte_perm(u0, u1, 0x7632);
    hp[1] = __byte_perm(u2, u3, 0x7632);
    float r0 = v.x - __uint_as_float(u0 & 0xffff0000u);
    float r1 = v.y - __uint_as_float(u1 & 0xffff0000u);
    float r2 = v.z - __uint_as_float(u2 & 0xffff0000u);
    float r3 = v.w - __uint_as_float(u3 & 0xffff0000u);
    __nv_bfloat162 l01 = __floats2bfloat162_rn(r0, r1);
    __nv_bfloat162 l23 = __floats2bfloat162_rn(r2, r3);
    lp[0] = *(uint32_t*)&l01;
    lp[1] = *(uint32_t*)&l23;
}

__device__ __forceinline__ uint32_t pack_hi2(float a, float b) {
    return __byte_perm(__float_as_uint(a), __float_as_uint(b), 0x7632);
}
__device__ __forceinline__ uint32_t pack_lo2(float a, float b) {
    float ra = a - __uint_as_float(__float_as_uint(a) & 0xffff0000u);
    float rb = b - __uint_as_float(__float_as_uint(b) & 0xffff0000u);
    __nv_bfloat162 l = __floats2bfloat162_rn(ra, rb);
    return *(uint32_t*)&l;
}
__device__ __forceinline__ uint32_t pack_rn2(float a, float b) {
    __nv_bfloat162 t = __floats2bfloat162_rn(a, b);
    return *(uint32_t*)&t;
}
__device__ __forceinline__ uint32_t pack_h2(float a, float b) {   // lo=a, hi=b
    __half2 t = __floats2half2_rn(a, b);
    return *(uint32_t*)&t;
}
__device__ __forceinline__ uint32_t ex2_f16x2(uint32_t x) {
    uint32_t r;
    asm volatile("ex2.approx.f16x2 %0, %1;" : "=r"(r) : "r"(x));
    return r;
}

// ================= conversions =============================================
#define C_S0 (MTOK*DM/4)
#define C_S1 (DM*DM/4)
#define C_S2 (2*DM*DM/4)
#define C_S3 (DM*DM/4)
#define C_TOT (C_S0+C_S1+C_S2+C_S3)

__global__ void __launch_bounds__(256) conv_all(
    const float* __restrict__ dec, const float* __restrict__ Wq,
    const float* __restrict__ Wkv, const float* __restrict__ Wo,
    __nv_bfloat16* __restrict__ db, __nv_bfloat16* __restrict__ wqb,
    __nv_bfloat16* __restrict__ wkvb, __nv_bfloat16* __restrict__ wob)
{
    int i = blockIdx.x * 256 + threadIdx.x;
    if (i >= C_TOT) return;
    const float* src; __nv_bfloat16* dst; int off;
    if (i < C_S0)                { src = dec; dst = db;  off = i; }
    else if (i < C_S0+C_S1)      { src = Wq;  dst = wqb; off = i - C_S0; }
    else if (i < C_S0+C_S1+C_S2) { src = Wkv; dst = wkvb;off = i - C_S0 - C_S1; }
    else                         { src = Wo;  dst = wob; off = i - C_S0 - C_S1 - C_S2; }
    float4 v = ((const float4*)src)[off];
    ((uint2*)dst)[off] = make_uint2(pack_rn2(v.x, v.y), pack_rn2(v.z, v.w));
}

__global__ void __launch_bounds__(256) conv_split(
    const float* __restrict__ x, __nv_bfloat16* __restrict__ h,
    __nv_bfloat16* __restrict__ l, int n4)
{
    int i = blockIdx.x * 256 + threadIdx.x;
    if (i >= n4) return;
    float4 v = ((const float4*)x)[i];
    uint32_t hp[2], lp[2];
    split4(v, hp, lp);
    ((uint2*)h)[i] = make_uint2(hp[0], hp[1]);
    ((uint2*)l)[i] = make_uint2(lp[0], lp[1]);
}

// ===================== single-plane bf16 GEMM core (3-stage, 1 sync) =======
#define SP_BYTES 10240
#define SSTAGE_BYTES (2 * SP_BYTES)
#define SSMEM_BYTES (3 * SSTAGE_BYTES)    // 61440

template<typename EPI>
__device__ __forceinline__ void gemm_sp_core(
    const __nv_bfloat16* __restrict__ Abase,
    const __nv_bfloat16* __restrict__ Bbase,
    int K, unsigned char* smraw, EPI&& epi)
{
    uint32_t sbase = (uint32_t)__cvta_generic_to_shared(smraw);
    const int tid  = threadIdx.x;
    const int lane = tid & 31;
    const int wid  = tid >> 5;
    const int wm   = wid >> 2;
    const int wn   = wid & 3;

    const int plane = tid >> 7;
    const __nv_bfloat16* srcbase = plane ? Bbase : Abase;

    auto issue = [&](int chunk, int buf) {
        int k0 = chunk * 32;
        uint32_t dbase = sbase + buf * SSTAGE_BYTES + plane * SP_BYTES;
        #pragma unroll
        for (int i = 0; i < 4; i++) {
            int ch = (tid & 127) + 128 * i;
            int row = ch >> 2, c = ch & 3;
            cp16(dbase + row * 80 + c * 16,
                 srcbase + (size_t)row * K + k0 + c * 8);
        }
        CP_COMMIT();
    };

    float acc[4][4][4] = {};

    const uint32_t arow = lane & 15;
    const uint32_t acol = ((lane >> 4) & 1) * 8;
    const uint32_t brow = (lane & 7) + ((lane >> 4) & 1) * 8;
    const uint32_t bcol = ((lane >> 3) & 1) * 8;

    auto compute = [&](int buf) {
        uint32_t base = sbase + buf * SSTAGE_BYTES;
        #pragma unroll
        for (int s = 0; s < 2; s++) {
            uint32_t ah[4][4], bh[2][4];
            #pragma unroll
            for (int mt = 0; mt < 4; mt++) {
                uint32_t off = (((wm * 64 + mt * 16 + arow) * 40) + acol + s * 16) << 1;
                ldsm_x4(ah[mt], base + off);
            }
            #pragma unroll
            for (int np = 0; np < 2; np++) {
                uint32_t off = (((wn * 32 + np * 16 + brow) * 40) + bcol + s * 16) << 1;
                ldsm_x4(bh[np], base + SP_BYTES + off);
            }
            #pragma unroll
            for (int mt = 0; mt < 4; mt++)
                #pragma unroll
                for (int nt = 0; nt < 4; nt++) {
                    int p = nt >> 1, q = (nt & 1) * 2;
                    mma16816(acc[mt][nt], ah[mt][0], ah[mt][1], ah[mt][2], ah[mt][3],
                             bh[p][q], bh[p][q + 1]);
                }
        }
    };

    const int NC = K >> 5;
    issue(0, 0);
    issue(1, 1);
    for (int c = 0; c < NC; c++) {
        CP_WAIT(1);
        __syncthreads();
        if (c + 2 < NC) issue(c + 2, (c + 2) % 3);
        else CP_COMMIT();
        compute(c % 3);
    }

    #pragma unroll
    for (int mt = 0; mt < 4; mt++)
        #pragma unroll
        for (int nt = 0; nt < 4; nt++) {
            int rr = wm * 64 + mt * 16 + (lane >> 2);
            int cc = wn * 32 + nt * 8 + (lane & 3) * 2;
            epi(rr, cc, acc[mt][nt]);
        }
}

// merged q+kv projection. kv V-half (bn>=1024) emitted as fp16.
__global__ void __launch_bounds__(256, 2) gemm_qkv(
    const __nv_bfloat16* __restrict__ db,
    const __nv_bfloat16* __restrict__ wqb, const __nv_bfloat16* __restrict__ wkvb,
    __nv_bfloat16* __restrict__ qb, __nv_bfloat16* __restrict__ kvb)
{
    extern __shared__ __align__(16) unsigned char smraw[];
    const int bm = blockIdx.y * 128;
    bool isq = blockIdx.x < 8;
    int bn = (isq ? blockIdx.x : (blockIdx.x - 8)) * 128;
    const __nv_bfloat16* B = (isq ? wqb : wkvb) + (size_t)bn * DM;
    __nv_bfloat16* C = isq ? qb : kvb;
    int N = isq ? 1024 : 2048;
    bool isv = (!isq) && (bn >= 1024);
    gemm_sp_core(db + (size_t)bm * DM, B, DM, smraw,
        [&](int rr, int cc, float a[4]) {
            size_t o0 = (size_t)(bm + rr) * N + bn + cc;
            size_t o1 = (size_t)(bm + rr + 8) * N + bn + cc;
            if (isv) {
                ((uint32_t*)C)[o0 >> 1] = pack_h2(a[0], a[1]);
                ((uint32_t*)C)[o1 >> 1] = pack_h2(a[2], a[3]);
            } else {
                ((uint32_t*)C)[o0 >> 1] = pack_rn2(a[0], a[1]);
                ((uint32_t*)C)[o1 >> 1] = pack_rn2(a[2], a[3]);
            }
        });
}

__global__ void __launch_bounds__(256, 2) gemm_wo(
    const __nv_bfloat16* __restrict__ vecb, const __nv_bfloat16* __restrict__ wob,
    const float* __restrict__ dec, float* __restrict__ h0)
{
    extern __shared__ __align__(16) unsigned char smraw[];
    const int bm = blockIdx.y * 128;
    const int bn = blockIdx.x * 128;
    gemm_sp_core(vecb + (size_t)bm * DM, wob + (size_t)bn * DM, DM, smraw,
        [&](int rr, int cc, float a[4]) {
            size_t o0 = (size_t)(bm + rr) * DM + bn + cc;
            size_t o1 = (size_t)(bm + rr + 8) * DM + bn + cc;
            float2 x0 = *(const float2*)&dec[o0];
            float2 x1 = *(const float2*)&dec[o1];
            *(float2*)&h0[o0] = make_float2(a[0] + x0.x, a[1] + x0.y);
            *(float2*)&h0[o1] = make_float2(a[2] + x1.x, a[3] + x1.y);
        });
}

// ===================== split-3x GEMM (Wff path, accuracy-critical) ========
#define GP_BYTES  10240
#define GSTAGE_BYTES (4 * GP_BYTES)
#define GSMEM_BYTES (2 * GSTAGE_BYTES)   // 81920

__global__ void __launch_bounds__(256, 2) gemm_ff(
    const __nv_bfloat16* __restrict__ Ah, const __nv_bfloat16* __restrict__ Al,
    const __nv_bfloat16* __restrict__ Bh, const __nv_bfloat16* __restrict__ Bl,
    const __nv_bfloat16* __restrict__ AddH, const __nv_bfloat16* __restrict__ AddL,
    float* __restrict__ Cf, int M, int N, int K)
{
    extern __shared__ __align__(16) unsigned char smraw[];
    uint32_t sbase = (uint32_t)__cvta_generic_to_shared(smraw);

    const int tid  = threadIdx.x;
    const int lane = tid & 31;
    const int wid  = tid >> 5;
    const int wm   = wid >> 2;
    const int wn   = wid & 3;
    const int bm   = blockIdx.y * 128;
    const int bn   = blockIdx.x * 128;

    const int plane = tid >> 6;
    const __nv_bfloat16* srcbase =
        (plane == 0) ? Ah + (size_t)bm * K :
        (plane == 1) ? Al + (size_t)bm * K :
        (plane == 2) ? Bh + (size_t)bn * K :
                       Bl + (size_t)bn * K;

    auto issue = [&](int k0, int buf) {
        uint32_t dbase = sbase + buf * GSTAGE_BYTES + plane * GP_BYTES;
        #pragma unroll
        for (int i = 0; i < 8; i++) {
            int chunk = (tid & 63) + 64 * i;
            int row = chunk >> 2, c = chunk & 3;
            cp16(dbase + row * 80 + c * 16,
                 srcbase + (size_t)row * K + k0 + c * 8);
        }
        CP_COMMIT();
    };

    float acc[4][4][4] = {};

    const uint32_t arow = lane & 15;
    const uint32_t acol = ((lane >> 4) & 1) * 8;
    const uint32_t brow = (lane & 7) + ((lane >> 4) & 1) * 8;
    const uint32_t bcol = ((lane >> 3) & 1) * 8;

    auto compute = [&](int buf) {
        uint32_t base = sbase + buf * GSTAGE_BYTES;
        #pragma unroll
        for (int s = 0; s < 2; s++) {
            uint32_t ah[4][4], al[4][4], bh[2][4], bl[2][4];
            #pragma unroll
            for (int mt = 0; mt < 4; mt++) {
                uint32_t off = (((wm * 64 + mt * 16 + arow) * 40) + acol + s * 16) << 1;
                ldsm_x4(ah[mt], base + off);
                ldsm_x4(al[mt], base + GP_BYTES + off);
            }
            #pragma unroll
            for (int np = 0; np < 2; np++) {
                uint32_t off = (((wn * 32 + np * 16 + brow) * 40) + bcol + s * 16) << 1;
                ldsm_x4(bh[np], base + 2 * GP_BYTES + off);
                ldsm_x4(bl[np], base + 3 * GP_BYTES + off);
            }
            #pragma unroll
            for (int mt = 0; mt < 4; mt++)
                #pragma unroll
                for (int nt = 0; nt < 4; nt++) {
                    int p = nt >> 1, q = (nt & 1) * 2;
                    mma16816(acc[mt][nt], ah[mt][0], ah[mt][1], ah[mt][2], ah[mt][3],
                             bh[p][q], bh[p][q + 1]);
                    mma16816(acc[mt][nt], ah[mt][0], ah[mt][1], ah[mt][2], ah[mt][3],
                             bl[p][q], bl[p][q + 1]);
                    mma16816(acc[mt][nt], al[mt][0], al[mt][1], al[mt][2], al[mt][3],
                             bh[p][q], bh[p][q + 1]);
                }
        }
    };

    issue(0, 0);
    issue(32, 1);
    CP_WAIT(1);
    __syncthreads();

    for (int k0 = 0; k0 < K; k0 += 32) {
        int buf = (k0 >> 5) & 1;
        compute(buf);
        __syncthreads();
        if (k0 + 64 < K) issue(k0 + 64, buf);
        if (k0 + 32 < K) { CP_WAIT(1); __syncthreads(); }
    }

    #pragma unroll
    for (int mt = 0; mt < 4; mt++) {
        #pragma unroll
        for (int nt = 0; nt < 4; nt++) {
            int r0 = bm + wm * 64 + mt * 16 + (lane >> 2);
            int c  = bn + wn * 32 + nt * 8 + (lane & 3) * 2;
            float a0 = acc[mt][nt][0], a1 = acc[mt][nt][1];
            float a2 = acc[mt][nt][2], a3 = acc[mt][nt][3];
            size_t o0 = (size_t)r0 * N + c, o1 = (size_t)(r0 + 8) * N + c;
            __nv_bfloat162 h0v = *(const __nv_bfloat162*)&AddH[o0];
            __nv_bfloat162 l0v = *(const __nv_bfloat162*)&AddL[o0];
            __nv_bfloat162 h1v = *(const __nv_bfloat162*)&AddH[o1];
            __nv_bfloat162 l1v = *(const __nv_bfloat162*)&AddL[o1];
            a0 += __bfloat162float(h0v.x) + __bfloat162float(l0v.x);
            a1 += __bfloat162float(h0v.y) + __bfloat162float(l0v.y);
            a2 += __bfloat162float(h1v.x) + __bfloat162float(l1v.x);
            a3 += __bfloat162float(h1v.y) + __bfloat162float(l1v.y);
            *(float2*)&Cf[o0] = make_float2(a0, a1);
            *(float2*)&Cf[o1] = make_float2(a2, a3);
        }
    }
}

// ================= bf16/fp16 flash attention — f16x2 softmax ==============
// QK in bf16; P computed via ex2.approx.f16x2 (1 MUFU / 2 elems, output is
// directly a packed fp16 MMA A-operand); PV in fp16 (V stored fp16).
#define AP 72
#define QP (256 * AP)                   // 18432 elems
#define KP (64 * AP)                    // 4608
#define AST (2 * KP)                    // K,V = 9216 elems
#define ASMEM_BYTES ((QP + 3 * AST) * 2)   // 92160
#define L2E 1.4426950408889634f

__global__ void __launch_bounds__(256) attn_sp(
    const __nv_bfloat16* __restrict__ qb, const __nv_bfloat16* __restrict__ kvb,
    __nv_bfloat16* __restrict__ vecb)
{
    extern __shared__ __align__(16) unsigned char smraw[];
    uint32_t sbase = (uint32_t)__cvta_generic_to_shared(smraw);

    const int tid  = threadIdx.x;
    const int lane = tid & 31;
    const int wid  = tid >> 5;                 // 0..7, owns rows wid*32..+31
    const int i0   = blockIdx.x * 256;
    const int b    = blockIdx.y;
    const int n    = blockIdx.z;

    // ---- Q staging ----
    {
        const __nv_bfloat16* src0 = qb + (size_t)b * 1024 + n * 64;
        #pragma unroll
        for (int i = 0; i < 8; i++) {
            int chunk = tid + 256 * i;
            int row = chunk >> 3, c = chunk & 7;
            cp16(sbase + row * 144 + c * 16,
                 src0 + (size_t)(i0 + row) * 2048 + c * 8);
        }
    }

    // ---- KV staging: 2 planes (K,V), 128 threads/plane ----
    const int plane = tid >> 7;                // 0=K, 1=V
    const __nv_bfloat16* kvsrc = kvb + (size_t)b * 2048 + n * 64 + plane * 1024;

    auto issue_kv = [&](int jt, int buf) {
        int j0 = jt * 64;
        uint32_t dbase = sbase + (QP + buf * AST + plane * KP) * 2;
        #pragma unroll
        for (int i = 0; i < 4; i++) {
            int chunk = (tid & 127) + 128 * i;
            int row = chunk >> 3, c = chunk & 7;
            cp16(dbase + row * 144 + c * 16,
                 kvsrc + (size_t)(j0 + row) * 4096 + c * 8);
        }
        CP_COMMIT();
    };

    issue_kv(0, 0);
    issue_kv(1, 1);
    CP_WAIT(1);
    __syncthreads();

    // ---- Q fragments persistent in registers (2 m-tiles) ----
    const uint32_t arow = lane & 15;
    const uint32_t acol = (lane >> 4) * 8;
    uint32_t qf[2][4][4];
    #pragma unroll
    for (int mt = 0; mt < 2; mt++)
        #pragma unroll
        for (int kc = 0; kc < 4; kc++) {
            uint32_t off = ((wid * 32 + mt * 16 + arow) * AP + kc * 16 + acol) * 2;
            ldsm_x4(qf[mt][kc], sbase + off);
        }

    const uint32_t brow = (lane & 7) + ((lane >> 4) & 1) * 8;
    const uint32_t bcol = ((lane >> 3) & 1) * 8;
    const uint32_t vrow = lane & 15;
    const uint32_t vcol = (lane >> 4) * 8;

    float acc_o[2][8][4] = {};
    float l[2][2] = {};
    const float SCL2 = 0.125f * L2E;
    const int NT = SEQ / 64;

    for (int jt = 0; jt < NT; jt++) {
        if (jt) { CP_WAIT(1); __syncthreads(); }
        if (jt + 2 < NT) issue_kv(jt + 2, (jt + 2) % 3);
        else CP_COMMIT();

        uint32_t stg = sbase + (QP + (jt % 3) * AST) * 2;

        // ---- S = Q K^T (shared B-frags across both m-tiles) ----
        float s_acc[2][8][4] = {};
        #pragma unroll
        for (int kc = 0; kc < 4; kc++) {
            uint32_t bh[4][4];
            #pragma unroll
            for (int np = 0; np < 4; np++) {
                uint32_t off = ((np * 16 + brow) * AP + kc * 16 + bcol) * 2;
                ldsm_x4(bh[np], stg + off);
            }
            #pragma unroll
            for (int mt = 0; mt < 2; mt++)
                #pragma unroll
                for (int nt = 0; nt < 8; nt++) {
                    int p = nt >> 1, qd = (nt & 1) * 2;
                    mma16816(s_acc[mt][nt], qf[mt][kc][0], qf[mt][kc][1],
                             qf[mt][kc][2], qf[mt][kc][3],
                             bh[p][qd], bh[p][qd + 1]);
                }
        }

        // ---- P = ex2.f16x2(s*SCL2): packed fp16 pairs, hadd2 row sums ----
        uint32_t pa[2][4][4];
        #pragma unroll
        for (int mt = 0; mt < 2; mt++) {
            __half2 la0 = __float2half2_rn(0.f);
            __half2 la1 = __float2half2_rn(0.f);
            #pragma unroll
            for (int kc = 0; kc < 4; kc++) {
                uint32_t p00 = ex2_f16x2(pack_h2(s_acc[mt][2*kc][0]   * SCL2,
                                                 s_acc[mt][2*kc][1]   * SCL2));
                uint32_t p01 = ex2_f16x2(pack_h2(s_acc[mt][2*kc][2]   * SCL2,
                                                 s_acc[mt][2*kc][3]   * SCL2));
                uint32_t p10 = ex2_f16x2(pack_h2(s_acc[mt][2*kc+1][0] * SCL2,
                                                 s_acc[mt][2*kc+1][1] * SCL2));
                uint32_t p11 = ex2_f16x2(pack_h2(s_acc[mt][2*kc+1][2] * SCL2,
                                                 s_acc[mt][2*kc+1][3] * SCL2));
                pa[mt][kc][0] = p00; pa[mt][kc][1] = p01;
                pa[mt][kc][2] = p10; pa[mt][kc][3] = p11;
                la0 = __hadd2(la0, *(__half2*)&p00);
                la0 = __hadd2(la0, *(__half2*)&p10);
                la1 = __hadd2(la1, *(__half2*)&p01);
                la1 = __hadd2(la1, *(__half2*)&p11);
            }
            float2 f0 = __half22float2(la0);
            float2 f1 = __half22float2(la1);
            l[mt][0] += f0.x + f0.y;
            l[mt][1] += f1.x + f1.y;
        }

        // ---- O += P V (fp16 MMA; V frags shared across both m-tiles) ----
        #pragma unroll
        for (int kc = 0; kc < 4; kc++) {
            uint32_t vh[4][4];
            #pragma unroll
            for (int np = 0; np < 4; np++) {
                uint32_t off = ((kc * 16 + vrow) * AP + np * 16 + vcol) * 2;
                ldsm_x4_t(vh[np], stg + KP * 2 + off);
            }
            #pragma unroll
            for (int mt = 0; mt < 2; mt++)
                #pragma unroll
                for (int nt = 0; nt < 8; nt++) {
                    int p = nt >> 1, qd = (nt & 1) * 2;
                    mma16816h(acc_o[mt][nt], pa[mt][kc][0], pa[mt][kc][1],
                              pa[mt][kc][2], pa[mt][kc][3],
                              vh[p][qd], vh[p][qd + 1]);
                }
        }
    }

    // ---- final row-sum reduce + epilogue ----
    #pragma unroll
    for (int mt = 0; mt < 2; mt++) {
        #pragma unroll
        for (int off = 1; off <= 2; off <<= 1) {
            l[mt][0] += __shfl_xor_sync(0xffffffffu, l[mt][0], off);
            l[mt][1] += __shfl_xor_sync(0xffffffffu, l[mt][1], off);
        }
        float inv0 = 1.f / l[mt][0], inv1 = 1.f / l[mt][1];
        int row0 = i0 + wid * 32 + mt * 16 + (lane >> 2);
        int colb = n * 64 + (lane & 3) * 2;
        #pragma unroll
        for (int nt = 0; nt < 8; nt++) {
            float a0 = acc_o[mt][nt][0] * inv0, a1 = acc_o[mt][nt][1] * inv0;
            float a2 = acc_o[mt][nt][2] * inv1, a3 = acc_o[mt][nt][3] * inv1;
            size_t o0 = ((size_t)row0 * 2 + b) * 1024 + colb + nt * 8;
            size_t o1 = ((size_t)(row0 + 8) * 2 + b) * 1024 + colb + nt * 8;
            ((uint32_t*)vecb)[o0 >> 1] = pack_rn2(a0, a1);
            ((uint32_t*)vecb)[o1 >> 1] = pack_rn2(a2, a3);
        }
    }
}

// ================= LayerNorm kernels ======================================
__device__ __forceinline__ void block_stats(float4 v, int t, float& mean, float& rstd)
{
    __shared__ float as[8], aq[8];
    float s  = v.x + v.y + v.z + v.w;
    float ss = v.x*v.x + v.y*v.y + v.z*v.z + v.w*v.w;
    #pragma unroll
    for (int off = 16; off; off >>= 1) {
        s  += __shfl_xor_sync(0xffffffffu, s, off);
        ss += __shfl_xor_sync(0xffffffffu, ss, off);
    }
    if ((t & 31) == 0) { as[t >> 5] = s; aq[t >> 5] = ss; }
    __syncthreads();
    s = 0.f; ss = 0.f;
    #pragma unroll
    for (int w = 0; w < 8; w++) { s += as[w]; ss += aq[w]; }
    mean = s * (1.f / 1024.f);
    float var = ss * (1.f / 1024.f) - mean * mean;
    rstd = rsqrtf(var + 1e-5f);
}

__global__ void __launch_bounds__(256) ln_kernel(
    const float* __restrict__ x, const float* __restrict__ g,
    const float* __restrict__ bt, __nv_bfloat16* __restrict__ yh,
    __nv_bfloat16* __restrict__ yl)
{
    int row = blockIdx.x;
    int t = threadIdx.x;
    float4 v = *(const float4*)&x[(size_t)row * 1024 + t * 4];
    float mean, rstd;
    block_stats(v, t, mean, rstd);
    float4 gv = *(const float4*)&g[t * 4];
    float4 bv = *(const float4*)&bt[t * 4];
    float o0 = (v.x - mean) * rstd * gv.x + bv.x;
    float o1 = (v.y - mean) * rstd * gv.y + bv.y;
    float o2 = (v.z - mean) * rstd * gv.z + bv.z;
    float o3 = (v.w - mean) * rstd * gv.w + bv.w;
    size_t idx = ((size_t)row * 1024 + t * 4) >> 1;
    ((uint2*)yh)[idx >> 1] = make_uint2(pack_hi2(o0, o1), pack_hi2(o2, o3));
    ((uint2*)yl)[idx >> 1] = make_uint2(pack_lo2(o0, o1), pack_lo2(o2, o3));
}

__global__ void __launch_bounds__(256) ln_final_kernel(
    const float* __restrict__ x, const float* __restrict__ g,
    const float* __restrict__ bt, float* __restrict__ y)
{
    int row = blockIdx.x;
    int t = threadIdx.x;
    float4 v = *(const float4*)&x[(size_t)row * 1024 + t * 4];
    float mean, rstd;
    block_stats(v, t, mean, rstd);
    float4 gv = *(const float4*)&g[t * 4];
    float4 bv = *(const float4*)&bt[t * 4];
    float ln[4] = {
        (v.x - mean) * rstd * gv.x + bv.x,
        (v.y - mean) * rstd * gv.y + bv.y,
        (v.z - mean) * rstd * gv.z + bv.z,
        (v.w - mean) * rstd * gv.w + bv.w
    };
    float bcol = (float)(row & 1);
    float o4[4];
    #pragma unroll
    for (int j = 0; j < 4; j++) {
        int d = t * 4 + j;
        float e = (float)(d & ~1) * (1.f / 1024.f);
        float freq = __expf(-9.210340371976184f * e);
        float ang = bcol * freq;
        float pe = (d & 1) ? cosf(ang) : sinf(ang);
        o4[j] = 2.f * ln[j] + pe;
    }
    float4 o; o.x = o4[0]; o.y = o4[1]; o.z = o4[2]; o.w = o4[3];
    *(float4*)&y[(size_t)row * 1024 + t * 4] = o;
}

// ================= launch ==================================================
extern "C" void kernel_launch(void* const* d_in, const int* in_sizes, int n_in,
                              void* d_out, int out_size)
{
    const float* dec = (const float*)d_in[0];
    const float* Wq  = (const float*)d_in[1];
    const float* Wkv = (const float*)d_in[2];
    const float* Wo  = (const float*)d_in[3];
    const float* g1  = (const float*)d_in[4];
    const float* b1  = (const float*)d_in[5];
    const float* Wff = (const float*)d_in[6];
    const float* g2  = (const float*)d_in[7];
    const float* b2  = (const float*)d_in[8];
    float* out = (float*)d_out;

    __nv_bfloat16 *db, *wqb, *wkvb, *wob, *wffh, *wffl;
    __nv_bfloat16 *qbp, *kvbp, *vecbp, *h1h, *h1l;
    float *h0, *f0;
    cudaGetSymbolAddress((void**)&db, g_db);
    cudaGetSymbolAddress((void**)&wqb, g_wqb);
    cudaGetSymbolAddress((void**)&wkvb, g_wkvb);
    cudaGetSymbolAddress((void**)&wob, g_wob);
    cudaGetSymbolAddress((void**)&wffh, g_wffh); cudaGetSymbolAddress((void**)&wffl, g_wffl);
    cudaGetSymbolAddress((void**)&qbp, g_qb);
    cudaGetSymbolAddress((void**)&kvbp, g_kvb);
    cudaGetSymbolAddress((void**)&vecbp, g_vecb);
    cudaGetSymbolAddress((void**)&h1h, g_h1h);   cudaGetSymbolAddress((void**)&h1l, g_h1l);
    cudaGetSymbolAddress((void**)&h0, g_h0);     cudaGetSymbolAddress((void**)&f0, g_f0);

    cudaFuncSetAttribute(gemm_qkv, cudaFuncAttributeMaxDynamicSharedMemorySize, SSMEM_BYTES);
    cudaFuncSetAttribute(gemm_wo, cudaFuncAttributeMaxDynamicSharedMemorySize, SSMEM_BYTES);
    cudaFuncSetAttribute(gemm_ff, cudaFuncAttributeMaxDynamicSharedMemorySize, GSMEM_BYTES);
    cudaFuncSetAttribute(attn_sp, cudaFuncAttributeMaxDynamicSharedMemorySize, ASMEM_BYTES);

    // conversions (fused rn + split for Wff)
    conv_all<<<(C_TOT + 255)/256, 256>>>(dec, Wq, Wkv, Wo, db, wqb, wkvb, wob);
    conv_split<<<(DM*DM/4 + 255)/256, 256>>>(Wff, wffh, wffl, DM*DM/4);

    // q + kv projections (merged launch; V half emitted fp16)
    gemm_qkv<<<dim3(24, 32), 256, SSMEM_BYTES>>>(db, wqb, wkvb, qbp, kvbp);
    // attention -> vec bf16 (f16x2 softmax, fp16 PV)
    attn_sp<<<dim3(SEQ/256, BATCH, NH), 256, ASMEM_BYTES>>>(qbp, kvbp, vecbp);
    // h0 = dec + vec @ Wo^T (fp32)
    gemm_wo<<<dim3(8, 32), 256, SSMEM_BYTES>>>(vecbp, wob, dec, h0);
    // h1 = LN(h0) -> hi/lo planes
    ln_kernel<<<MTOK, 256>>>(h0, g1, b1, h1h, h1l);
    // f0 = h1 + h1 @ Wff^T (split-3x, accuracy-critical)
    gemm_ff<<<dim3(8, 32), 256, GSMEM_BYTES>>>(
        h1h, h1l, wffh, wffl, h1h, h1l, f0, MTOK, 1024, 1024);
    // out = 2*LN(f0) + pe[b]
    ln_final_kernel<<<MTOK, 256>>>(f0, g2, b2, out);
}

// round 16
// speedup vs baseline: 1.0649x; 1.0649x over previous
#include <cuda_runtime.h>
#include <cuda_bf16.h>
#include <cstdint>

// Problem constants
#define SEQ   2048
#define BATCH 2
#define DM    1024
#define NH    16
#define DH    64
#define MTOK  (SEQ*BATCH)   // 4096 token rows

// ---------------- scratch (device globals) --------------------------------
__device__ __nv_bfloat16 g_db [MTOK * DM];              // dec, bf16 rn
__device__ __nv_bfloat16 g_wqb[DM * DM];
__device__ __nv_bfloat16 g_wkvb[2 * DM * DM];
__device__ __nv_bfloat16 g_wob[DM * DM];
__device__ __nv_bfloat16 g_wffh[DM * DM], g_wffl[DM * DM];
__device__ __nv_bfloat16 g_qb [MTOK * DM];
__device__ __nv_bfloat16 g_kvb[MTOK * 2 * DM];          // [token][K|V]
__device__ __nv_bfloat16 g_vecb[MTOK * DM];
__device__ __nv_bfloat16 g_h1h[MTOK * DM], g_h1l[MTOK * DM];
__device__ float g_h0[MTOK * DM];
__device__ float g_f0[MTOK * DM];

// ===================== common helpers ======================================
__device__ __forceinline__ void ldsm_x4(uint32_t r[4], uint32_t addr) {
    asm volatile("ldmatrix.sync.aligned.m8n8.x4.shared.b16 {%0,%1,%2,%3}, [%4];\n"
                 : "=r"(r[0]), "=r"(r[1]), "=r"(r[2]), "=r"(r[3]) : "r"(addr));
}
__device__ __forceinline__ void ldsm_x4_t(uint32_t r[4], uint32_t addr) {
    asm volatile("ldmatrix.sync.aligned.m8n8.x4.trans.shared.b16 {%0,%1,%2,%3}, [%4];\n"
                 : "=r"(r[0]), "=r"(r[1]), "=r"(r[2]), "=r"(r[3]) : "r"(addr));
}

__device__ __forceinline__ void mma16816(float c[4],
                                         uint32_t a0, uint32_t a1, uint32_t a2, uint32_t a3,
                                         uint32_t b0, uint32_t b1) {
    asm volatile(
        "mma.sync.aligned.m16n8k16.row.col.f32.bf16.bf16.f32 "
        "{%0,%1,%2,%3}, {%4,%5,%6,%7}, {%8,%9}, {%0,%1,%2,%3};\n"
        : "+f"(c[0]), "+f"(c[1]), "+f"(c[2]), "+f"(c[3])
        : "r"(a0), "r"(a1), "r"(a2), "r"(a3), "r"(b0), "r"(b1));
}

__device__ __forceinline__ void cp16(uint32_t dst, const void* src) {
    asm volatile("cp.async.cg.shared.global [%0], [%1], 16;\n" :: "r"(dst), "l"(src));
}
#define CP_COMMIT()  asm volatile("cp.async.commit_group;\n")
#define CP_WAIT(n)   asm volatile("cp.async.wait_group %0;\n" :: "n"(n))

__device__ __forceinline__ void split4(float4 v, uint32_t hp[2], uint32_t lp[2]) {
    uint32_t u0 = __float_as_uint(v.x), u1 = __float_as_uint(v.y);
    uint32_t u2 = __float_as_uint(v.z), u3 = __float_as_uint(v.w);
    hp[0] = __byte_perm(u0, u1, 0x7632);
    hp[1] = __byte_perm(u2, u3, 0x7632);
    float r0 = v.x - __uint_as_float(u0 & 0xffff0000u);
    float r1 = v.y - __uint_as_float(u1 & 0xffff0000u);
    float r2 = v.z - __uint_as_float(u2 & 0xffff0000u);
    float r3 = v.w - __uint_as_float(u3 & 0xffff0000u);
    __nv_bfloat162 l01 = __floats2bfloat162_rn(r0, r1);
    __nv_bfloat162 l23 = __floats2bfloat162_rn(r2, r3);
    lp[0] = *(uint32_t*)&l01;
    lp[1] = *(uint32_t*)&l23;
}

__device__ __forceinline__ uint32_t pack_hi2(float a, float b) {
    return __byte_perm(__float_as_uint(a), __float_as_uint(b), 0x7632);
}
__device__ __forceinline__ uint32_t pack_lo2(float a, float b) {
    float ra = a - __uint_as_float(__float_as_uint(a) & 0xffff0000u);
    float rb = b - __uint_as_float(__float_as_uint(b) & 0xffff0000u);
    __nv_bfloat162 l = __floats2bfloat162_rn(ra, rb);
    return *(uint32_t*)&l;
}
__device__ __forceinline__ uint32_t pack_rn2(float a, float b) {
    __nv_bfloat162 t = __floats2bfloat162_rn(a, b);
    return *(uint32_t*)&t;
}

// ================= conversions =============================================
#define C_S0 (MTOK*DM/4)
#define C_S1 (DM*DM/4)
#define C_S2 (2*DM*DM/4)
#define C_S3 (DM*DM/4)
#define C_TOT (C_S0+C_S1+C_S2+C_S3)

__global__ void __launch_bounds__(256) conv_all(
    const float* __restrict__ dec, const float* __restrict__ Wq,
    const float* __restrict__ Wkv, const float* __restrict__ Wo,
    __nv_bfloat16* __restrict__ db, __nv_bfloat16* __restrict__ wqb,
    __nv_bfloat16* __restrict__ wkvb, __nv_bfloat16* __restrict__ wob)
{
    int i = blockIdx.x * 256 + threadIdx.x;
    if (i >= C_TOT) return;
    const float* src; __nv_bfloat16* dst; int off;
    if (i < C_S0)                { src = dec; dst = db;  off = i; }
    else if (i < C_S0+C_S1)      { src = Wq;  dst = wqb; off = i - C_S0; }
    else if (i < C_S0+C_S1+C_S2) { src = Wkv; dst = wkvb;off = i - C_S0 - C_S1; }
    else                         { src = Wo;  dst = wob; off = i - C_S0 - C_S1 - C_S2; }
    float4 v = ((const float4*)src)[off];
    ((uint2*)dst)[off] = make_uint2(pack_rn2(v.x, v.y), pack_rn2(v.z, v.w));
}

__global__ void __launch_bounds__(256) conv_split(
    const float* __restrict__ x, __nv_bfloat16* __restrict__ h,
    __nv_bfloat16* __restrict__ l, int n4)
{
    int i = blockIdx.x * 256 + threadIdx.x;
    if (i >= n4) return;
    float4 v = ((const float4*)x)[i];
    uint32_t hp[2], lp[2];
    split4(v, hp, lp);
    ((uint2*)h)[i] = make_uint2(hp[0], hp[1]);
    ((uint2*)l)[i] = make_uint2(lp[0], lp[1]);
}

// ===================== single-plane bf16 GEMM core (3-stage, 1 sync) =======
#define SP_BYTES 10240
#define SSTAGE_BYTES (2 * SP_BYTES)
#define SSMEM_BYTES (3 * SSTAGE_BYTES)    // 61440

template<typename EPI>
__device__ __forceinline__ void gemm_sp_core(
    const __nv_bfloat16* __restrict__ Abase,
    const __nv_bfloat16* __restrict__ Bbase,
    int K, unsigned char* smraw, EPI&& epi)
{
    uint32_t sbase = (uint32_t)__cvta_generic_to_shared(smraw);
    const int tid  = threadIdx.x;
    const int lane = tid & 31;
    const int wid  = tid >> 5;
    const int wm   = wid >> 2;
    const int wn   = wid & 3;

    const int plane = tid >> 7;
    const __nv_bfloat16* srcbase = plane ? Bbase : Abase;

    auto issue = [&](int chunk, int buf) {
        int k0 = chunk * 32;
        uint32_t dbase = sbase + buf * SSTAGE_BYTES + plane * SP_BYTES;
        #pragma unroll
        for (int i = 0; i < 4; i++) {
            int ch = (tid & 127) + 128 * i;
            int row = ch >> 2, c = ch & 3;
            cp16(dbase + row * 80 + c * 16,
                 srcbase + (size_t)row * K + k0 + c * 8);
        }
        CP_COMMIT();
    };

    float acc[4][4][4] = {};

    const uint32_t arow = lane & 15;
    const uint32_t acol = ((lane >> 4) & 1) * 8;
    const uint32_t brow = (lane & 7) + ((lane >> 4) & 1) * 8;
    const uint32_t bcol = ((lane >> 3) & 1) * 8;

    auto compute = [&](int buf) {
        uint32_t base = sbase + buf * SSTAGE_BYTES;
        #pragma unroll
        for (int s = 0; s < 2; s++) {
            uint32_t ah[4][4], bh[2][4];
            #pragma unroll
            for (int mt = 0; mt < 4; mt++) {
                uint32_t off = (((wm * 64 + mt * 16 + arow) * 40) + acol + s * 16) << 1;
                ldsm_x4(ah[mt], base + off);
            }
            #pragma unroll
            for (int np = 0; np < 2; np++) {
                uint32_t off = (((wn * 32 + np * 16 + brow) * 40) + bcol + s * 16) << 1;
                ldsm_x4(bh[np], base + SP_BYTES + off);
            }
            #pragma unroll
            for (int mt = 0; mt < 4; mt++)
                #pragma unroll
                for (int nt = 0; nt < 4; nt++) {
                    int p = nt >> 1, q = (nt & 1) * 2;
                    mma16816(acc[mt][nt], ah[mt][0], ah[mt][1], ah[mt][2], ah[mt][3],
                             bh[p][q], bh[p][q + 1]);
                }
        }
    };

    const int NC = K >> 5;
    issue(0, 0);
    issue(1, 1);
    for (int c = 0; c < NC; c++) {
        CP_WAIT(1);
        __syncthreads();
        if (c + 2 < NC) issue(c + 2, (c + 2) % 3);
        else CP_COMMIT();
        compute(c % 3);
    }

    #pragma unroll
    for (int mt = 0; mt < 4; mt++)
        #pragma unroll
        for (int nt = 0; nt < 4; nt++) {
            int rr = wm * 64 + mt * 16 + (lane >> 2);
            int cc = wn * 32 + nt * 8 + (lane & 3) * 2;
            epi(rr, cc, acc[mt][nt]);
        }
}

__global__ void __launch_bounds__(256, 2) gemm_qkv(
    const __nv_bfloat16* __restrict__ db,
    const __nv_bfloat16* __restrict__ wqb, const __nv_bfloat16* __restrict__ wkvb,
    __nv_bfloat16* __restrict__ qb, __nv_bfloat16* __restrict__ kvb)
{
    extern __shared__ __align__(16) unsigned char smraw[];
    const int bm = blockIdx.y * 128;
    bool isq = blockIdx.x < 8;
    int bn = (isq ? blockIdx.x : (blockIdx.x - 8)) * 128;
    const __nv_bfloat16* B = (isq ? wqb : wkvb) + (size_t)bn * DM;
    __nv_bfloat16* C = isq ? qb : kvb;
    int N = isq ? 1024 : 2048;
    gemm_sp_core(db + (size_t)bm * DM, B, DM, smraw,
        [&](int rr, int cc, float a[4]) {
            size_t o0 = (size_t)(bm + rr) * N + bn + cc;
            size_t o1 = (size_t)(bm + rr + 8) * N + bn + cc;
            ((uint32_t*)C)[o0 >> 1] = pack_rn2(a[0], a[1]);
            ((uint32_t*)C)[o1 >> 1] = pack_rn2(a[2], a[3]);
        });
}

__global__ void __launch_bounds__(256, 2) gemm_wo(
    const __nv_bfloat16* __restrict__ vecb, const __nv_bfloat16* __restrict__ wob,
    const float* __restrict__ dec, float* __restrict__ h0)
{
    extern __shared__ __align__(16) unsigned char smraw[];
    const int bm = blockIdx.y * 128;
    const int bn = blockIdx.x * 128;
    gemm_sp_core(vecb + (size_t)bm * DM, wob + (size_t)bn * DM, DM, smraw,
        [&](int rr, int cc, float a[4]) {
            size_t o0 = (size_t)(bm + rr) * DM + bn + cc;
            size_t o1 = (size_t)(bm + rr + 8) * DM + bn + cc;
            float2 x0 = *(const float2*)&dec[o0];
            float2 x1 = *(const float2*)&dec[o1];
            *(float2*)&h0[o0] = make_float2(a[0] + x0.x, a[1] + x0.y);
            *(float2*)&h0[o1] = make_float2(a[2] + x1.x, a[3] + x1.y);
        });
}

// ===================== split-3x GEMM (Wff path, accuracy-critical) ========
#define GP_BYTES  10240
#define GSTAGE_BYTES (4 * GP_BYTES)
#define GSMEM_BYTES (2 * GSTAGE_BYTES)   // 81920

__global__ void __launch_bounds__(256, 2) gemm_ff(
    const __nv_bfloat16* __restrict__ Ah, const __nv_bfloat16* __restrict__ Al,
    const __nv_bfloat16* __restrict__ Bh, const __nv_bfloat16* __restrict__ Bl,
    const __nv_bfloat16* __restrict__ AddH, const __nv_bfloat16* __restrict__ AddL,
    float* __restrict__ Cf, int M, int N, int K)
{
    extern __shared__ __align__(16) unsigned char smraw[];
    uint32_t sbase = (uint32_t)__cvta_generic_to_shared(smraw);

    const int tid  = threadIdx.x;
    const int lane = tid & 31;
    const int wid  = tid >> 5;
    const int wm   = wid >> 2;
    const int wn   = wid & 3;
    const int bm   = blockIdx.y * 128;
    const int bn   = blockIdx.x * 128;

    const int plane = tid >> 6;
    const __nv_bfloat16* srcbase =
        (plane == 0) ? Ah + (size_t)bm * K :
        (plane == 1) ? Al + (size_t)bm * K :
        (plane == 2) ? Bh + (size_t)bn * K :
                       Bl + (size_t)bn * K;

    auto issue = [&](int k0, int buf) {
        uint32_t dbase = sbase + buf * GSTAGE_BYTES + plane * GP_BYTES;
        #pragma unroll
        for (int i = 0; i < 8; i++) {
            int chunk = (tid & 63) + 64 * i;
            int row = chunk >> 2, c = chunk & 3;
            cp16(dbase + row * 80 + c * 16,
                 srcbase + (size_t)row * K + k0 + c * 8);
        }
        CP_COMMIT();
    };

    float acc[4][4][4] = {};

    const uint32_t arow = lane & 15;
    const uint32_t acol = ((lane >> 4) & 1) * 8;
    const uint32_t brow = (lane & 7) + ((lane >> 4) & 1) * 8;
    const uint32_t bcol = ((lane >> 3) & 1) * 8;

    auto compute = [&](int buf) {
        uint32_t base = sbase + buf * GSTAGE_BYTES;
        #pragma unroll
        for (int s = 0; s < 2; s++) {
            uint32_t ah[4][4], al[4][4], bh[2][4], bl[2][4];
            #pragma unroll
            for (int mt = 0; mt < 4; mt++) {
                uint32_t off = (((wm * 64 + mt * 16 + arow) * 40) + acol + s * 16) << 1;
                ldsm_x4(ah[mt], base + off);
                ldsm_x4(al[mt], base + GP_BYTES + off);
            }
            #pragma unroll
            for (int np = 0; np < 2; np++) {
                uint32_t off = (((wn * 32 + np * 16 + brow) * 40) + bcol + s * 16) << 1;
                ldsm_x4(bh[np], base + 2 * GP_BYTES + off);
                ldsm_x4(bl[np], base + 3 * GP_BYTES + off);
            }
            #pragma unroll
            for (int mt = 0; mt < 4; mt++)
                #pragma unroll
                for (int nt = 0; nt < 4; nt++) {
                    int p = nt >> 1, q = (nt & 1) * 2;
                    mma16816(acc[mt][nt], ah[mt][0], ah[mt][1], ah[mt][2], ah[mt][3],
                             bh[p][q], bh[p][q + 1]);
                    mma16816(acc[mt][nt], ah[mt][0], ah[mt][1], ah[mt][2], ah[mt][3],
                             bl[p][q], bl[p][q + 1]);
                    mma16816(acc[mt][nt], al[mt][0], al[mt][1], al[mt][2], al[mt][3],
                             bh[p][q], bh[p][q + 1]);
                }
        }
    };

    issue(0, 0);
    issue(32, 1);
    CP_WAIT(1);
    __syncthreads();

    for (int k0 = 0; k0 < K; k0 += 32) {
        int buf = (k0 >> 5) & 1;
        compute(buf);
        __syncthreads();
        if (k0 + 64 < K) issue(k0 + 64, buf);
        if (k0 + 32 < K) { CP_WAIT(1); __syncthreads(); }
    }

    #pragma unroll
    for (int mt = 0; mt < 4; mt++) {
        #pragma unroll
        for (int nt = 0; nt < 4; nt++) {
            int r0 = bm + wm * 64 + mt * 16 + (lane >> 2);
            int c  = bn + wn * 32 + nt * 8 + (lane & 3) * 2;
            float a0 = acc[mt][nt][0], a1 = acc[mt][nt][1];
            float a2 = acc[mt][nt][2], a3 = acc[mt][nt][3];
            size_t o0 = (size_t)r0 * N + c, o1 = (size_t)(r0 + 8) * N + c;
            __nv_bfloat162 h0v = *(const __nv_bfloat162*)&AddH[o0];
            __nv_bfloat162 l0v = *(const __nv_bfloat162*)&AddL[o0];
            __nv_bfloat162 h1v = *(const __nv_bfloat162*)&AddH[o1];
            __nv_bfloat162 l1v = *(const __nv_bfloat162*)&AddL[o1];
            a0 += __bfloat162float(h0v.x) + __bfloat162float(l0v.x);
            a1 += __bfloat162float(h0v.y) + __bfloat162float(l0v.y);
            a2 += __bfloat162float(h1v.x) + __bfloat162float(l1v.x);
            a3 += __bfloat162float(h1v.y) + __bfloat162float(l1v.y);
            *(float2*)&Cf[o0] = make_float2(a0, a1);
            *(float2*)&Cf[o1] = make_float2(a2, a3);
        }
    }
}

// ================= bf16 flash attention — 128 q-rows, 2 CTAs/SM ===========
// 4 warps x 32-row tiles, 128 threads, 73.7KB smem -> 2 CTAs co-resident
// per SM (cross-CTA latency cover that single-CTA configs lacked).
#define AP 72
#define QP (128 * AP)                   // 9216 elems
#define KP (64 * AP)                    // 4608
#define AST (2 * KP)                    // K,V = 9216 elems
#define ASMEM_BYTES ((QP + 3 * AST) * 2)   // 73728
#define L2E 1.4426950408889634f

__global__ void __launch_bounds__(128, 2) attn_sp(
    const __nv_bfloat16* __restrict__ qb, const __nv_bfloat16* __restrict__ kvb,
    __nv_bfloat16* __restrict__ vecb)
{
    extern __shared__ __align__(16) unsigned char smraw[];
    uint32_t sbase = (uint32_t)__cvta_generic_to_shared(smraw);

    const int tid  = threadIdx.x;
    const int lane = tid & 31;
    const int wid  = tid >> 5;                 // 0..3, owns rows wid*32..+31
    const int i0   = blockIdx.x * 128;
    const int b    = blockIdx.y;
    const int n    = blockIdx.z;

    // ---- Q staging: 128 rows x 8 chunks of 16B (1024 chunks / 128 thr) ----
    {
        const __nv_bfloat16* src0 = qb + (size_t)b * 1024 + n * 64;
        #pragma unroll
        for (int i = 0; i < 8; i++) {
            int chunk = tid + 128 * i;
            int row = chunk >> 3, c = chunk & 7;
            cp16(sbase + row * 144 + c * 16,
                 src0 + (size_t)(i0 + row) * 2048 + c * 8);
        }
    }

    // ---- KV staging: 2 planes (K,V), 64 threads/plane, 8 chunks each ----
    const int plane = tid >> 6;                // 0=K, 1=V
    const __nv_bfloat16* kvsrc = kvb + (size_t)b * 2048 + n * 64 + plane * 1024;

    auto issue_kv = [&](int jt, int buf) {
        int j0 = jt * 64;
        uint32_t dbase = sbase + (QP + buf * AST + plane * KP) * 2;
        #pragma unroll
        for (int i = 0; i < 8; i++) {
            int chunk = (tid & 63) + 64 * i;   // 0..511
            int row = chunk >> 3, c = chunk & 7;
            cp16(dbase + row * 144 + c * 16,
                 kvsrc + (size_t)(j0 + row) * 4096 + c * 8);
        }
        CP_COMMIT();
    };

    issue_kv(0, 0);     // group 0 includes Q + tile 0
    issue_kv(1, 1);
    CP_WAIT(1);
    __syncthreads();

    // ---- Q fragments persistent in registers (2 m-tiles per warp) ----
    const uint32_t arow = lane & 15;
    const uint32_t acol = (lane >> 4) * 8;
    uint32_t qf[2][4][4];
    #pragma unroll
    for (int mt = 0; mt < 2; mt++)
        #pragma unroll
        for (int kc = 0; kc < 4; kc++) {
            uint32_t off = ((wid * 32 + mt * 16 + arow) * AP + kc * 16 + acol) * 2;
            ldsm_x4(qf[mt][kc], sbase + off);
        }

    const uint32_t brow = (lane & 7) + ((lane >> 4) & 1) * 8;
    const uint32_t bcol = ((lane >> 3) & 1) * 8;
    const uint32_t vrow = lane & 15;
    const uint32_t vcol = (lane >> 4) * 8;

    float acc_o[2][8][4] = {};
    float l[2][2] = {};
    const float SCL2 = 0.125f * L2E;
    const int NT = SEQ / 64;

    for (int jt = 0; jt < NT; jt++) {
        if (jt) { CP_WAIT(1); __syncthreads(); }
        if (jt + 2 < NT) issue_kv(jt + 2, (jt + 2) % 3);
        else CP_COMMIT();

        uint32_t stg = sbase + (QP + (jt % 3) * AST) * 2;

        // ---- S = Q K^T (shared B-frags across both m-tiles) ----
        float s_acc[2][8][4] = {};
        #pragma unroll
        for (int kc = 0; kc < 4; kc++) {
            uint32_t bh[4][4];
            #pragma unroll
            for (int np = 0; np < 4; np++) {
                uint32_t off = ((np * 16 + brow) * AP + kc * 16 + bcol) * 2;
                ldsm_x4(bh[np], stg + off);
            }
            #pragma unroll
            for (int mt = 0; mt < 2; mt++)
                #pragma unroll
                for (int nt = 0; nt < 8; nt++) {
                    int p = nt >> 1, qd = (nt & 1) * 2;
                    mma16816(s_acc[mt][nt], qf[mt][kc][0], qf[mt][kc][1],
                             qf[mt][kc][2], qf[mt][kc][3],
                             bh[p][qd], bh[p][qd + 1]);
                }
        }

        // ---- P = exp2(s*SCL2); accumulate l; pack ----
        uint32_t pa[2][4][4];
        #pragma unroll
        for (int mt = 0; mt < 2; mt++) {
            #pragma unroll
            for (int nt = 0; nt < 8; nt++) {
                float p0 = exp2f(s_acc[mt][nt][0] * SCL2);
                float p1 = exp2f(s_acc[mt][nt][1] * SCL2);
                float p2 = exp2f(s_acc[mt][nt][2] * SCL2);
                float p3 = exp2f(s_acc[mt][nt][3] * SCL2);
                l[mt][0] += p0 + p1; l[mt][1] += p2 + p3;
                s_acc[mt][nt][0] = p0; s_acc[mt][nt][1] = p1;
                s_acc[mt][nt][2] = p2; s_acc[mt][nt][3] = p3;
            }
            #pragma unroll
            for (int kc = 0; kc < 4; kc++) {
                pa[mt][kc][0] = pack_rn2(s_acc[mt][2*kc][0],   s_acc[mt][2*kc][1]);
                pa[mt][kc][1] = pack_rn2(s_acc[mt][2*kc][2],   s_acc[mt][2*kc][3]);
                pa[mt][kc][2] = pack_rn2(s_acc[mt][2*kc+1][0], s_acc[mt][2*kc+1][1]);
                pa[mt][kc][3] = pack_rn2(s_acc[mt][2*kc+1][2], s_acc[mt][2*kc+1][3]);
            }
        }

        // ---- O += P V (shared V-frags across both m-tiles) ----
        #pragma unroll
        for (int kc = 0; kc < 4; kc++) {
            uint32_t vh[4][4];
            #pragma unroll
            for (int np = 0; np < 4; np++) {
                uint32_t off = ((kc * 16 + vrow) * AP + np * 16 + vcol) * 2;
                ldsm_x4_t(vh[np], stg + KP * 2 + off);
            }
            #pragma unroll
            for (int mt = 0; mt < 2; mt++)
                #pragma unroll
                for (int nt = 0; nt < 8; nt++) {
                    int p = nt >> 1, qd = (nt & 1) * 2;
                    mma16816(acc_o[mt][nt], pa[mt][kc][0], pa[mt][kc][1],
                             pa[mt][kc][2], pa[mt][kc][3],
                             vh[p][qd], vh[p][qd + 1]);
                }
        }
    }

    // ---- final row-sum reduce + epilogue ----
    #pragma unroll
    for (int mt = 0; mt < 2; mt++) {
        #pragma unroll
        for (int off = 1; off <= 2; off <<= 1) {
            l[mt][0] += __shfl_xor_sync(0xffffffffu, l[mt][0], off);
            l[mt][1] += __shfl_xor_sync(0xffffffffu, l[mt][1], off);
        }
        float inv0 = 1.f / l[mt][0], inv1 = 1.f / l[mt][1];
        int row0 = i0 + wid * 32 + mt * 16 + (lane >> 2);
        int colb = n * 64 + (lane & 3) * 2;
        #pragma unroll
        for (int nt = 0; nt < 8; nt++) {
            float a0 = acc_o[mt][nt][0] * inv0, a1 = acc_o[mt][nt][1] * inv0;
            float a2 = acc_o[mt][nt][2] * inv1, a3 = acc_o[mt][nt][3] * inv1;
            size_t o0 = ((size_t)row0 * 2 + b) * 1024 + colb + nt * 8;
            size_t o1 = ((size_t)(row0 + 8) * 2 + b) * 1024 + colb + nt * 8;
            ((uint32_t*)vecb)[o0 >> 1] = pack_rn2(a0, a1);
            ((uint32_t*)vecb)[o1 >> 1] = pack_rn2(a2, a3);
        }
    }
}

// ================= LayerNorm kernels ======================================
__device__ __forceinline__ void block_stats(float4 v, int t, float& mean, float& rstd)
{
    __shared__ float as[8], aq[8];
    float s  = v.x + v.y + v.z + v.w;
    float ss = v.x*v.x + v.y*v.y + v.z*v.z + v.w*v.w;
    #pragma unroll
    for (int off = 16; off; off >>= 1) {
        s  += __shfl_xor_sync(0xffffffffu, s, off);
        ss += __shfl_xor_sync(0xffffffffu, ss, off);
    }
    if ((t & 31) == 0) { as[t >> 5] = s; aq[t >> 5] = ss; }
    __syncthreads();
    s = 0.f; ss = 0.f;
    #pragma unroll
    for (int w = 0; w < 8; w++) { s += as[w]; ss += aq[w]; }
    mean = s * (1.f / 1024.f);
    float var = ss * (1.f / 1024.f) - mean * mean;
    rstd = rsqrtf(var + 1e-5f);
}

__global__ void __launch_bounds__(256) ln_kernel(
    const float* __restrict__ x, const float* __restrict__ g,
    const float* __restrict__ bt, __nv_bfloat16* __restrict__ yh,
    __nv_bfloat16* __restrict__ yl)
{
    int row = blockIdx.x;
    int t = threadIdx.x;
    float4 v = *(const float4*)&x[(size_t)row * 1024 + t * 4];
    float mean, rstd;
    block_stats(v, t, mean, rstd);
    float4 gv = *(const float4*)&g[t * 4];
    float4 bv = *(const float4*)&bt[t * 4];
    float o0 = (v.x - mean) * rstd * gv.x + bv.x;
    float o1 = (v.y - mean) * rstd * gv.y + bv.y;
    float o2 = (v.z - mean) * rstd * gv.z + bv.z;
    float o3 = (v.w - mean) * rstd * gv.w + bv.w;
    size_t idx = ((size_t)row * 1024 + t * 4) >> 1;
    ((uint2*)yh)[idx >> 1] = make_uint2(pack_hi2(o0, o1), pack_hi2(o2, o3));
    ((uint2*)yl)[idx >> 1] = make_uint2(pack_lo2(o0, o1), pack_lo2(o2, o3));
}

__global__ void __launch_bounds__(256) ln_final_kernel(
    const float* __restrict__ x, const float* __restrict__ g,
    const float* __restrict__ bt, float* __restrict__ y)
{
    int row = blockIdx.x;
    int t = threadIdx.x;
    float4 v = *(const float4*)&x[(size_t)row * 1024 + t * 4];
    float mean, rstd;
    block_stats(v, t, mean, rstd);
    float4 gv = *(const float4*)&g[t * 4];
    float4 bv = *(const float4*)&bt[t * 4];
    float ln[4] = {
        (v.x - mean) * rstd * gv.x + bv.x,
        (v.y - mean) * rstd * gv.y + bv.y,
        (v.z - mean) * rstd * gv.z + bv.z,
        (v.w - mean) * rstd * gv.w + bv.w
    };
    float bcol = (float)(row & 1);
    float o4[4];
    #pragma unroll
    for (int j = 0; j < 4; j++) {
        int d = t * 4 + j;
        float e = (float)(d & ~1) * (1.f / 1024.f);
        float freq = __expf(-9.210340371976184f * e);
        float ang = bcol * freq;
        float pe = (d & 1) ? cosf(ang) : sinf(ang);
        o4[j] = 2.f * ln[j] + pe;
    }
    float4 o; o.x = o4[0]; o.y = o4[1]; o.z = o4[2]; o.w = o4[3];
    *(float4*)&y[(size_t)row * 1024 + t * 4] = o;
}

// ================= launch ==================================================
extern "C" void kernel_launch(void* const* d_in, const int* in_sizes, int n_in,
                              void* d_out, int out_size)
{
    const float* dec = (const float*)d_in[0];
    const float* Wq  = (const float*)d_in[1];
    const float* Wkv = (const float*)d_in[2];
    const float* Wo  = (const float*)d_in[3];
    const float* g1  = (const float*)d_in[4];
    const float* b1  = (const float*)d_in[5];
    const float* Wff = (const float*)d_in[6];
    const float* g2  = (const float*)d_in[7];
    const float* b2  = (const float*)d_in[8];
    float* out = (float*)d_out;

    __nv_bfloat16 *db, *wqb, *wkvb, *wob, *wffh, *wffl;
    __nv_bfloat16 *qbp, *kvbp, *vecbp, *h1h, *h1l;
    float *h0, *f0;
    cudaGetSymbolAddress((void**)&db, g_db);
    cudaGetSymbolAddress((void**)&wqb, g_wqb);
    cudaGetSymbolAddress((void**)&wkvb, g_wkvb);
    cudaGetSymbolAddress((void**)&wob, g_wob);
    cudaGetSymbolAddress((void**)&wffh, g_wffh); cudaGetSymbolAddress((void**)&wffl, g_wffl);
    cudaGetSymbolAddress((void**)&qbp, g_qb);
    cudaGetSymbolAddress((void**)&kvbp, g_kvb);
    cudaGetSymbolAddress((void**)&vecbp, g_vecb);
    cudaGetSymbolAddress((void**)&h1h, g_h1h);   cudaGetSymbolAddress((void**)&h1l, g_h1l);
    cudaGetSymbolAddress((void**)&h0, g_h0);     cudaGetSymbolAddress((void**)&f0, g_f0);

    cudaFuncSetAttribute(gemm_qkv, cudaFuncAttributeMaxDynamicSharedMemorySize, SSMEM_BYTES);
    cudaFuncSetAttribute(gemm_wo, cudaFuncAttributeMaxDynamicSharedMemorySize, SSMEM_BYTES);
    cudaFuncSetAttribute(gemm_ff, cudaFuncAttributeMaxDynamicSharedMemorySize, GSMEM_BYTES);
    cudaFuncSetAttribute(attn_sp, cudaFuncAttributeMaxDynamicSharedMemorySize, ASMEM_BYTES);

    // conversions (fused rn + split for Wff)
    conv_all<<<(C_TOT + 255)/256, 256>>>(dec, Wq, Wkv, Wo, db, wqb, wkvb, wob);
    conv_split<<<(DM*DM/4 + 255)/256, 256>>>(Wff, wffh, wffl, DM*DM/4);

    // q + kv projections (merged launch)
    gemm_qkv<<<dim3(24, 32), 256, SSMEM_BYTES>>>(db, wqb, wkvb, qbp, kvbp);
    // attention -> vec bf16 (128 q-rows/CTA, 2 CTAs/SM)
    attn_sp<<<dim3(SEQ/128, BATCH, NH), 128, ASMEM_BYTES>>>(qbp, kvbp, vecbp);
    // h0 = dec + vec @ Wo^T (fp32)
    gemm_wo<<<dim3(8, 32), 256, SSMEM_BYTES>>>(vecbp, wob, dec, h0);
    // h1 = LN(h0) -> hi/lo planes
    ln_kernel<<<MTOK, 256>>>(h0, g1, b1, h1h, h1l);
    // f0 = h1 + h1 @ Wff^T (split-3x, accuracy-critical)
    gemm_ff<<<dim3(8, 32), 256, GSMEM_BYTES>>>(
        h1h, h1l, wffh, wffl, h1h, h1l, f0, MTOK, 1024, 1024);
    // out = 2*LN(f0) + pe[b]
    ln_final_kernel<<<MTOK, 256>>>(f0, g2, b2, out);
}

// round 17
// speedup vs baseline: 1.2416x; 1.1660x over previous
#include <cuda_runtime.h>
#include <cuda_bf16.h>
#include <cuda_fp16.h>
#include <cstdint>

// Problem constants
#define SEQ   2048
#define BATCH 2
#define DM    1024
#define NH    16
#define DH    64
#define MTOK  (SEQ*BATCH)   // 4096 token rows

// ---------------- scratch (device globals) --------------------------------
__device__ __nv_bfloat16 g_db [MTOK * DM];              // dec, bf16 rn
__device__ __nv_bfloat16 g_wqb[DM * DM];
__device__ __nv_bfloat16 g_wkvb[2 * DM * DM];
__device__ __nv_bfloat16 g_wob[DM * DM];
__device__ __half        g_wff16[DM * DM];              // Wff, fp16
__device__ __nv_bfloat16 g_qb [MTOK * DM];
__device__ __nv_bfloat16 g_kvb[MTOK * 2 * DM];          // [token][K|V]
__device__ __nv_bfloat16 g_vecb[MTOK * DM];
__device__ __nv_bfloat16 g_h1h[MTOK * DM], g_h1l[MTOK * DM];  // residual (hi/lo exact)
__device__ __half        g_h1f[MTOK * DM];              // h1, fp16 (MMA operand)
__device__ float g_h0[MTOK * DM];
__device__ float g_f0[MTOK * DM];

// ===================== common helpers ======================================
__device__ __forceinline__ void ldsm_x4(uint32_t r[4], uint32_t addr) {
    asm volatile("ldmatrix.sync.aligned.m8n8.x4.shared.b16 {%0,%1,%2,%3}, [%4];\n"
                 : "=r"(r[0]), "=r"(r[1]), "=r"(r[2]), "=r"(r[3]) : "r"(addr));
}
__device__ __forceinline__ void ldsm_x4_t(uint32_t r[4], uint32_t addr) {
    asm volatile("ldmatrix.sync.aligned.m8n8.x4.trans.shared.b16 {%0,%1,%2,%3}, [%4];\n"
                 : "=r"(r[0]), "=r"(r[1]), "=r"(r[2]), "=r"(r[3]) : "r"(addr));
}

__device__ __forceinline__ void mma16816(float c[4],
                                         uint32_t a0, uint32_t a1, uint32_t a2, uint32_t a3,
                                         uint32_t b0, uint32_t b1) {
    asm volatile(
        "mma.sync.aligned.m16n8k16.row.col.f32.bf16.bf16.f32 "
        "{%0,%1,%2,%3}, {%4,%5,%6,%7}, {%8,%9}, {%0,%1,%2,%3};\n"
        : "+f"(c[0]), "+f"(c[1]), "+f"(c[2]), "+f"(c[3])
        : "r"(a0), "r"(a1), "r"(a2), "r"(a3), "r"(b0), "r"(b1));
}
__device__ __forceinline__ void mma16816h(float c[4],
                                          uint32_t a0, uint32_t a1, uint32_t a2, uint32_t a3,
                                          uint32_t b0, uint32_t b1) {
    asm volatile(
        "mma.sync.aligned.m16n8k16.row.col.f32.f16.f16.f32 "
        "{%0,%1,%2,%3}, {%4,%5,%6,%7}, {%8,%9}, {%0,%1,%2,%3};\n"
        : "+f"(c[0]), "+f"(c[1]), "+f"(c[2]), "+f"(c[3])
        : "r"(a0), "r"(a1), "r"(a2), "r"(a3), "r"(b0), "r"(b1));
}

__device__ __forceinline__ void cp16(uint32_t dst, const void* src) {
    asm volatile("cp.async.cg.shared.global [%0], [%1], 16;\n" :: "r"(dst), "l"(src));
}
#define CP_COMMIT()  asm volatile("cp.async.commit_group;\n")
#define CP_WAIT(n)   asm volatile("cp.async.wait_group %0;\n" :: "n"(n))

__device__ __forceinline__ uint32_t pack_hi2(float a, float b) {
    return __byte_perm(__float_as_uint(a), __float_as_uint(b), 0x7632);
}
__device__ __forceinline__ uint32_t pack_lo2(float a, float b) {
    float ra = a - __uint_as_float(__float_as_uint(a) & 0xffff0000u);
    float rb = b - __uint_as_float(__float_as_uint(b) & 0xffff0000u);
    __nv_bfloat162 l = __floats2bfloat162_rn(ra, rb);
    return *(uint32_t*)&l;
}
__device__ __forceinline__ uint32_t pack_rn2(float a, float b) {
    __nv_bfloat162 t = __floats2bfloat162_rn(a, b);
    return *(uint32_t*)&t;
}
__device__ __forceinline__ uint32_t pack_h2(float a, float b) {
    __half2 t = __floats2half2_rn(a, b);
    return *(uint32_t*)&t;
}

// ================= conversions =============================================
// fused: dec, Wq, Wkv, Wo -> bf16 rn; Wff -> fp16
#define C_S0 (MTOK*DM/4)
#define C_S1 (DM*DM/4)
#define C_S2 (2*DM*DM/4)
#define C_S3 (DM*DM/4)
#define C_S4 (DM*DM/4)
#define C_TOT (C_S0+C_S1+C_S2+C_S3+C_S4)

__global__ void __launch_bounds__(256) conv_all(
    const float* __restrict__ dec, const float* __restrict__ Wq,
    const float* __restrict__ Wkv, const float* __restrict__ Wo,
    const float* __restrict__ Wff,
    __nv_bfloat16* __restrict__ db, __nv_bfloat16* __restrict__ wqb,
    __nv_bfloat16* __restrict__ wkvb, __nv_bfloat16* __restrict__ wob,
    __half* __restrict__ wff16)
{
    int i = blockIdx.x * 256 + threadIdx.x;
    if (i >= C_TOT) return;
    if (i >= C_S0 + C_S1 + C_S2 + C_S3) {
        int off = i - C_S0 - C_S1 - C_S2 - C_S3;
        float4 v = ((const float4*)Wff)[off];
        ((uint2*)wff16)[off] = make_uint2(pack_h2(v.x, v.y), pack_h2(v.z, v.w));
        return;
    }
    const float* src; __nv_bfloat16* dst; int off;
    if (i < C_S0)                { src = dec; dst = db;  off = i; }
    else if (i < C_S0+C_S1)      { src = Wq;  dst = wqb; off = i - C_S0; }
    else if (i < C_S0+C_S1+C_S2) { src = Wkv; dst = wkvb;off = i - C_S0 - C_S1; }
    else                         { src = Wo;  dst = wob; off = i - C_S0 - C_S1 - C_S2; }
    float4 v = ((const float4*)src)[off];
    ((uint2*)dst)[off] = make_uint2(pack_rn2(v.x, v.y), pack_rn2(v.z, v.w));
}

// ===================== single-plane 16-bit GEMM core (3-stage, 1 sync) =====
// F16=0: bf16 MMA; F16=1: fp16 MMA. Operands are 2-byte, layout-identical.
#define SP_BYTES 10240
#define SSTAGE_BYTES (2 * SP_BYTES)
#define SSMEM_BYTES (3 * SSTAGE_BYTES)    // 61440

template<int F16, typename EPI>
__device__ __forceinline__ void gemm_sp_core(
    const __nv_bfloat16* __restrict__ Abase,
    const __nv_bfloat16* __restrict__ Bbase,
    int K, unsigned char* smraw, EPI&& epi)
{
    uint32_t sbase = (uint32_t)__cvta_generic_to_shared(smraw);
    const int tid  = threadIdx.x;
    const int lane = tid & 31;
    const int wid  = tid >> 5;
    const int wm   = wid >> 2;
    const int wn   = wid & 3;

    const int plane = tid >> 7;
    const __nv_bfloat16* srcbase = plane ? Bbase : Abase;

    auto issue = [&](int chunk, int buf) {
        int k0 = chunk * 32;
        uint32_t dbase = sbase + buf * SSTAGE_BYTES + plane * SP_BYTES;
        #pragma unroll
        for (int i = 0; i < 4; i++) {
            int ch = (tid & 127) + 128 * i;
            int row = ch >> 2, c = ch & 3;
            cp16(dbase + row * 80 + c * 16,
                 srcbase + (size_t)row * K + k0 + c * 8);
        }
        CP_COMMIT();
    };

    float acc[4][4][4] = {};

    const uint32_t arow = lane & 15;
    const uint32_t acol = ((lane >> 4) & 1) * 8;
    const uint32_t brow = (lane & 7) + ((lane >> 4) & 1) * 8;
    const uint32_t bcol = ((lane >> 3) & 1) * 8;

    auto compute = [&](int buf) {
        uint32_t base = sbase + buf * SSTAGE_BYTES;
        #pragma unroll
        for (int s = 0; s < 2; s++) {
            uint32_t ah[4][4], bh[2][4];
            #pragma unroll
            for (int mt = 0; mt < 4; mt++) {
                uint32_t off = (((wm * 64 + mt * 16 + arow) * 40) + acol + s * 16) << 1;
                ldsm_x4(ah[mt], base + off);
            }
            #pragma unroll
            for (int np = 0; np < 2; np++) {
                uint32_t off = (((wn * 32 + np * 16 + brow) * 40) + bcol + s * 16) << 1;
                ldsm_x4(bh[np], base + SP_BYTES + off);
            }
            #pragma unroll
            for (int mt = 0; mt < 4; mt++)
                #pragma unroll
                for (int nt = 0; nt < 4; nt++) {
                    int p = nt >> 1, q = (nt & 1) * 2;
                    if constexpr (F16)
                        mma16816h(acc[mt][nt], ah[mt][0], ah[mt][1], ah[mt][2], ah[mt][3],
                                  bh[p][q], bh[p][q + 1]);
                    else
                        mma16816(acc[mt][nt], ah[mt][0], ah[mt][1], ah[mt][2], ah[mt][3],
                                 bh[p][q], bh[p][q + 1]);
                }
        }
    };

    const int NC = K >> 5;
    issue(0, 0);
    issue(1, 1);
    for (int c = 0; c < NC; c++) {
        CP_WAIT(1);
        __syncthreads();
        if (c + 2 < NC) issue(c + 2, (c + 2) % 3);
        else CP_COMMIT();
        compute(c % 3);
    }

    #pragma unroll
    for (int mt = 0; mt < 4; mt++)
        #pragma unroll
        for (int nt = 0; nt < 4; nt++) {
            int rr = wm * 64 + mt * 16 + (lane >> 2);
            int cc = wn * 32 + nt * 8 + (lane & 3) * 2;
            epi(rr, cc, acc[mt][nt]);
        }
}

__global__ void __launch_bounds__(256, 2) gemm_qkv(
    const __nv_bfloat16* __restrict__ db,
    const __nv_bfloat16* __restrict__ wqb, const __nv_bfloat16* __restrict__ wkvb,
    __nv_bfloat16* __restrict__ qb, __nv_bfloat16* __restrict__ kvb)
{
    extern __shared__ __align__(16) unsigned char smraw[];
    const int bm = blockIdx.y * 128;
    bool isq = blockIdx.x < 8;
    int bn = (isq ? blockIdx.x : (blockIdx.x - 8)) * 128;
    const __nv_bfloat16* B = (isq ? wqb : wkvb) + (size_t)bn * DM;
    __nv_bfloat16* C = isq ? qb : kvb;
    int N = isq ? 1024 : 2048;
    gemm_sp_core<0>(db + (size_t)bm * DM, B, DM, smraw,
        [&](int rr, int cc, float a[4]) {
            size_t o0 = (size_t)(bm + rr) * N + bn + cc;
            size_t o1 = (size_t)(bm + rr + 8) * N + bn + cc;
            ((uint32_t*)C)[o0 >> 1] = pack_rn2(a[0], a[1]);
            ((uint32_t*)C)[o1 >> 1] = pack_rn2(a[2], a[3]);
        });
}

__global__ void __launch_bounds__(256, 2) gemm_wo(
    const __nv_bfloat16* __restrict__ vecb, const __nv_bfloat16* __restrict__ wob,
    const float* __restrict__ dec, float* __restrict__ h0)
{
    extern __shared__ __align__(16) unsigned char smraw[];
    const int bm = blockIdx.y * 128;
    const int bn = blockIdx.x * 128;
    gemm_sp_core<0>(vecb + (size_t)bm * DM, wob + (size_t)bn * DM, DM, smraw,
        [&](int rr, int cc, float a[4]) {
            size_t o0 = (size_t)(bm + rr) * DM + bn + cc;
            size_t o1 = (size_t)(bm + rr + 8) * DM + bn + cc;
            float2 x0 = *(const float2*)&dec[o0];
            float2 x1 = *(const float2*)&dec[o1];
            *(float2*)&h0[o0] = make_float2(a[0] + x0.x, a[1] + x0.y);
            *(float2*)&h0[o1] = make_float2(a[2] + x1.x, a[3] + x1.y);
        });
}

// ff GEMM: fp16 single-plane MMA; residual add from exact hi/lo bf16 planes.
__global__ void __launch_bounds__(256, 2) gemm_ff16(
    const __half* __restrict__ h1f, const __half* __restrict__ wff16,
    const __nv_bfloat16* __restrict__ AddH, const __nv_bfloat16* __restrict__ AddL,
    float* __restrict__ Cf)
{
    extern __shared__ __align__(16) unsigned char smraw[];
    const int bm = blockIdx.y * 128;
    const int bn = blockIdx.x * 128;
    gemm_sp_core<1>((const __nv_bfloat16*)(h1f + (size_t)bm * DM),
                    (const __nv_bfloat16*)(wff16 + (size_t)bn * DM), DM, smraw,
        [&](int rr, int cc, float a[4]) {
            size_t o0 = (size_t)(bm + rr) * DM + bn + cc;
            size_t o1 = (size_t)(bm + rr + 8) * DM + bn + cc;
            __nv_bfloat162 h0v = *(const __nv_bfloat162*)&AddH[o0];
            __nv_bfloat162 l0v = *(const __nv_bfloat162*)&AddL[o0];
            __nv_bfloat162 h1v = *(const __nv_bfloat162*)&AddH[o1];
            __nv_bfloat162 l1v = *(const __nv_bfloat162*)&AddL[o1];
            float r0 = a[0] + __bfloat162float(h0v.x) + __bfloat162float(l0v.x);
            float r1 = a[1] + __bfloat162float(h0v.y) + __bfloat162float(l0v.y);
            float r2 = a[2] + __bfloat162float(h1v.x) + __bfloat162float(l1v.x);
            float r3 = a[3] + __bfloat162float(h1v.y) + __bfloat162float(l1v.y);
            *(float2*)&Cf[o0] = make_float2(r0, r1);
            *(float2*)&Cf[o1] = make_float2(r2, r3);
        });
}

// ================= bf16 flash attention — 128 q-rows, 2 CTAs/SM ===========
#define AP 72
#define QP (128 * AP)                   // 9216 elems
#define KP (64 * AP)                    // 4608
#define AST (2 * KP)                    // K,V = 9216 elems
#define ASMEM_BYTES ((QP + 3 * AST) * 2)   // 73728
#define L2E 1.4426950408889634f

__global__ void __launch_bounds__(128, 2) attn_sp(
    const __nv_bfloat16* __restrict__ qb, const __nv_bfloat16* __restrict__ kvb,
    __nv_bfloat16* __restrict__ vecb)
{
    extern __shared__ __align__(16) unsigned char smraw[];
    uint32_t sbase = (uint32_t)__cvta_generic_to_shared(smraw);

    const int tid  = threadIdx.x;
    const int lane = tid & 31;
    const int wid  = tid >> 5;                 // 0..3, owns rows wid*32..+31
    const int i0   = blockIdx.x * 128;
    const int b    = blockIdx.y;
    const int n    = blockIdx.z;

    // ---- Q staging ----
    {
        const __nv_bfloat16* src0 = qb + (size_t)b * 1024 + n * 64;
        #pragma unroll
        for (int i = 0; i < 8; i++) {
            int chunk = tid + 128 * i;
            int row = chunk >> 3, c = chunk & 7;
            cp16(sbase + row * 144 + c * 16,
                 src0 + (size_t)(i0 + row) * 2048 + c * 8);
        }
    }

    // ---- KV staging: 2 planes (K,V), 64 threads/plane ----
    const int plane = tid >> 6;
    const __nv_bfloat16* kvsrc = kvb + (size_t)b * 2048 + n * 64 + plane * 1024;

    auto issue_kv = [&](int jt, int buf) {
        int j0 = jt * 64;
        uint32_t dbase = sbase + (QP + buf * AST + plane * KP) * 2;
        #pragma unroll
        for (int i = 0; i < 8; i++) {
            int chunk = (tid & 63) + 64 * i;
            int row = chunk >> 3, c = chunk & 7;
            cp16(dbase + row * 144 + c * 16,
                 kvsrc + (size_t)(j0 + row) * 4096 + c * 8);
        }
        CP_COMMIT();
    };

    issue_kv(0, 0);
    issue_kv(1, 1);
    CP_WAIT(1);
    __syncthreads();

    // ---- Q fragments persistent in registers (2 m-tiles per warp) ----
    const uint32_t arow = lane & 15;
    const uint32_t acol = (lane >> 4) * 8;
    uint32_t qf[2][4][4];
    #pragma unroll
    for (int mt = 0; mt < 2; mt++)
        #pragma unroll
        for (int kc = 0; kc < 4; kc++) {
            uint32_t off = ((wid * 32 + mt * 16 + arow) * AP + kc * 16 + acol) * 2;
            ldsm_x4(qf[mt][kc], sbase + off);
        }

    const uint32_t brow = (lane & 7) + ((lane >> 4) & 1) * 8;
    const uint32_t bcol = ((lane >> 3) & 1) * 8;
    const uint32_t vrow = lane & 15;
    const uint32_t vcol = (lane >> 4) * 8;

    float acc_o[2][8][4] = {};
    float l[2][2] = {};
    const float SCL2 = 0.125f * L2E;
    const int NT = SEQ / 64;

    for (int jt = 0; jt < NT; jt++) {
        if (jt) { CP_WAIT(1); __syncthreads(); }
        if (jt + 2 < NT) issue_kv(jt + 2, (jt + 2) % 3);
        else CP_COMMIT();

        uint32_t stg = sbase + (QP + (jt % 3) * AST) * 2;

        // ---- S = Q K^T ----
        float s_acc[2][8][4] = {};
        #pragma unroll
        for (int kc = 0; kc < 4; kc++) {
            uint32_t bh[4][4];
            #pragma unroll
            for (int np = 0; np < 4; np++) {
                uint32_t off = ((np * 16 + brow) * AP + kc * 16 + bcol) * 2;
                ldsm_x4(bh[np], stg + off);
            }
            #pragma unroll
            for (int mt = 0; mt < 2; mt++)
                #pragma unroll
                for (int nt = 0; nt < 8; nt++) {
                    int p = nt >> 1, qd = (nt & 1) * 2;
                    mma16816(s_acc[mt][nt], qf[mt][kc][0], qf[mt][kc][1],
                             qf[mt][kc][2], qf[mt][kc][3],
                             bh[p][qd], bh[p][qd + 1]);
                }
        }

        // ---- P = exp2(s*SCL2); accumulate l; pack ----
        uint32_t pa[2][4][4];
        #pragma unroll
        for (int mt = 0; mt < 2; mt++) {
            #pragma unroll
            for (int nt = 0; nt < 8; nt++) {
                float p0 = exp2f(s_acc[mt][nt][0] * SCL2);
                float p1 = exp2f(s_acc[mt][nt][1] * SCL2);
                float p2 = exp2f(s_acc[mt][nt][2] * SCL2);
                float p3 = exp2f(s_acc[mt][nt][3] * SCL2);
                l[mt][0] += p0 + p1; l[mt][1] += p2 + p3;
                s_acc[mt][nt][0] = p0; s_acc[mt][nt][1] = p1;
                s_acc[mt][nt][2] = p2; s_acc[mt][nt][3] = p3;
            }
            #pragma unroll
            for (int kc = 0; kc < 4; kc++) {
                pa[mt][kc][0] = pack_rn2(s_acc[mt][2*kc][0],   s_acc[mt][2*kc][1]);
                pa[mt][kc][1] = pack_rn2(s_acc[mt][2*kc][2],   s_acc[mt][2*kc][3]);
                pa[mt][kc][2] = pack_rn2(s_acc[mt][2*kc+1][0], s_acc[mt][2*kc+1][1]);
                pa[mt][kc][3] = pack_rn2(s_acc[mt][2*kc+1][2], s_acc[mt][2*kc+1][3]);
            }
        }

        // ---- O += P V ----
        #pragma unroll
        for (int kc = 0; kc < 4; kc++) {
            uint32_t vh[4][4];
            #pragma unroll
            for (int np = 0; np < 4; np++) {
                uint32_t off = ((kc * 16 + vrow) * AP + np * 16 + vcol) * 2;
                ldsm_x4_t(vh[np], stg + KP * 2 + off);
            }
            #pragma unroll
            for (int mt = 0; mt < 2; mt++)
                #pragma unroll
                for (int nt = 0; nt < 8; nt++) {
                    int p = nt >> 1, qd = (nt & 1) * 2;
                    mma16816(acc_o[mt][nt], pa[mt][kc][0], pa[mt][kc][1],
                             pa[mt][kc][2], pa[mt][kc][3],
                             vh[p][qd], vh[p][qd + 1]);
                }
        }
    }

    // ---- final row-sum reduce + epilogue ----
    #pragma unroll
    for (int mt = 0; mt < 2; mt++) {
        #pragma unroll
        for (int off = 1; off <= 2; off <<= 1) {
            l[mt][0] += __shfl_xor_sync(0xffffffffu, l[mt][0], off);
            l[mt][1] += __shfl_xor_sync(0xffffffffu, l[mt][1], off);
        }
        float inv0 = 1.f / l[mt][0], inv1 = 1.f / l[mt][1];
        int row0 = i0 + wid * 32 + mt * 16 + (lane >> 2);
        int colb = n * 64 + (lane & 3) * 2;
        #pragma unroll
        for (int nt = 0; nt < 8; nt++) {
            float a0 = acc_o[mt][nt][0] * inv0, a1 = acc_o[mt][nt][1] * inv0;
            float a2 = acc_o[mt][nt][2] * inv1, a3 = acc_o[mt][nt][3] * inv1;
            size_t o0 = ((size_t)row0 * 2 + b) * 1024 + colb + nt * 8;
            size_t o1 = ((size_t)(row0 + 8) * 2 + b) * 1024 + colb + nt * 8;
            ((uint32_t*)vecb)[o0 >> 1] = pack_rn2(a0, a1);
            ((uint32_t*)vecb)[o1 >> 1] = pack_rn2(a2, a3);
        }
    }
}

// ================= LayerNorm kernels ======================================
__device__ __forceinline__ void block_stats(float4 v, int t, float& mean, float& rstd)
{
    __shared__ float as[8], aq[8];
    float s  = v.x + v.y + v.z + v.w;
    float ss = v.x*v.x + v.y*v.y + v.z*v.z + v.w*v.w;
    #pragma unroll
    for (int off = 16; off; off >>= 1) {
        s  += __shfl_xor_sync(0xffffffffu, s, off);
        ss += __shfl_xor_sync(0xffffffffu, ss, off);
    }
    if ((t & 31) == 0) { as[t >> 5] = s; aq[t >> 5] = ss; }
    __syncthreads();
    s = 0.f; ss = 0.f;
    #pragma unroll
    for (int w = 0; w < 8; w++) { s += as[w]; ss += aq[w]; }
    mean = s * (1.f / 1024.f);
    float var = ss * (1.f / 1024.f) - mean * mean;
    rstd = rsqrtf(var + 1e-5f);
}

// LN1: fp32 in -> hi/lo bf16 planes (residual) + fp16 plane (MMA operand)
__global__ void __launch_bounds__(256) ln_kernel(
    const float* __restrict__ x, const float* __restrict__ g,
    const float* __restrict__ bt, __nv_bfloat16* __restrict__ yh,
    __nv_bfloat16* __restrict__ yl, __half* __restrict__ yf)
{
    int row = blockIdx.x;
    int t = threadIdx.x;
    float4 v = *(const float4*)&x[(size_t)row * 1024 + t * 4];
    float mean, rstd;
    block_stats(v, t, mean, rstd);
    float4 gv = *(const float4*)&g[t * 4];
    float4 bv = *(const float4*)&bt[t * 4];
    float o0 = (v.x - mean) * rstd * gv.x + bv.x;
    float o1 = (v.y - mean) * rstd * gv.y + bv.y;
    float o2 = (v.z - mean) * rstd * gv.z + bv.z;
    float o3 = (v.w - mean) * rstd * gv.w + bv.w;
    size_t idx = ((size_t)row * 1024 + t * 4) >> 1;
    ((uint2*)yh)[idx >> 1] = make_uint2(pack_hi2(o0, o1), pack_hi2(o2, o3));
    ((uint2*)yl)[idx >> 1] = make_uint2(pack_lo2(o0, o1), pack_lo2(o2, o3));
    ((uint2*)yf)[idx >> 1] = make_uint2(pack_h2(o0, o1), pack_h2(o2, o3));
}

__global__ void __launch_bounds__(256) ln_final_kernel(
    const float* __restrict__ x, const float* __restrict__ g,
    const float* __restrict__ bt, float* __restrict__ y)
{
    int row = blockIdx.x;
    int t = threadIdx.x;
    float4 v = *(const float4*)&x[(size_t)row * 1024 + t * 4];
    float mean, rstd;
    block_stats(v, t, mean, rstd);
    float4 gv = *(const float4*)&g[t * 4];
    float4 bv = *(const float4*)&bt[t * 4];
    float ln[4] = {
        (v.x - mean) * rstd * gv.x + bv.x,
        (v.y - mean) * rstd * gv.y + bv.y,
        (v.z - mean) * rstd * gv.z + bv.z,
        (v.w - mean) * rstd * gv.w + bv.w
    };
    float bcol = (float)(row & 1);
    float o4[4];
    #pragma unroll
    for (int j = 0; j < 4; j++) {
        int d = t * 4 + j;
        float e = (float)(d & ~1) * (1.f / 1024.f);
        float freq = __expf(-9.210340371976184f * e);
        float ang = bcol * freq;
        float pe = (d & 1) ? cosf(ang) : sinf(ang);
        o4[j] = 2.f * ln[j] + pe;
    }
    float4 o; o.x = o4[0]; o.y = o4[1]; o.z = o4[2]; o.w = o4[3];
    *(float4*)&y[(size_t)row * 1024 + t * 4] = o;
}

// ================= launch ==================================================
extern "C" void kernel_launch(void* const* d_in, const int* in_sizes, int n_in,
                              void* d_out, int out_size)
{
    const float* dec = (const float*)d_in[0];
    const float* Wq  = (const float*)d_in[1];
    const float* Wkv = (const float*)d_in[2];
    const float* Wo  = (const float*)d_in[3];
    const float* g1  = (const float*)d_in[4];
    const float* b1  = (const float*)d_in[5];
    const float* Wff = (const float*)d_in[6];
    const float* g2  = (const float*)d_in[7];
    const float* b2  = (const float*)d_in[8];
    float* out = (float*)d_out;

    __nv_bfloat16 *db, *wqb, *wkvb, *wob;
    __half *wff16, *h1f;
    __nv_bfloat16 *qbp, *kvbp, *vecbp, *h1h, *h1l;
    float *h0, *f0;
    cudaGetSymbolAddress((void**)&db, g_db);
    cudaGetSymbolAddress((void**)&wqb, g_wqb);
    cudaGetSymbolAddress((void**)&wkvb, g_wkvb);
    cudaGetSymbolAddress((void**)&wob, g_wob);
    cudaGetSymbolAddress((void**)&wff16, g_wff16);
    cudaGetSymbolAddress((void**)&qbp, g_qb);
    cudaGetSymbolAddress((void**)&kvbp, g_kvb);
    cudaGetSymbolAddress((void**)&vecbp, g_vecb);
    cudaGetSymbolAddress((void**)&h1h, g_h1h);   cudaGetSymbolAddress((void**)&h1l, g_h1l);
    cudaGetSymbolAddress((void**)&h1f, g_h1f);
    cudaGetSymbolAddress((void**)&h0, g_h0);     cudaGetSymbolAddress((void**)&f0, g_f0);

    cudaFuncSetAttribute(gemm_qkv, cudaFuncAttributeMaxDynamicSharedMemorySize, SSMEM_BYTES);
    cudaFuncSetAttribute(gemm_wo, cudaFuncAttributeMaxDynamicSharedMemorySize, SSMEM_BYTES);
    cudaFuncSetAttribute(gemm_ff16, cudaFuncAttributeMaxDynamicSharedMemorySize, SSMEM_BYTES);
    cudaFuncSetAttribute(attn_sp, cudaFuncAttributeMaxDynamicSharedMemorySize, ASMEM_BYTES);

    // conversions (fused)
    conv_all<<<(C_TOT + 255)/256, 256>>>(dec, Wq, Wkv, Wo, Wff,
                                         db, wqb, wkvb, wob, wff16);

    // q + kv projections (merged launch)
    gemm_qkv<<<dim3(24, 32), 256, SSMEM_BYTES>>>(db, wqb, wkvb, qbp, kvbp);
    // attention -> vec bf16 (128 q-rows/CTA, 2 CTAs/SM)
    attn_sp<<<dim3(SEQ/128, BATCH, NH), 128, ASMEM_BYTES>>>(qbp, kvbp, vecbp);
    // h0 = dec + vec @ Wo^T (fp32)
    gemm_wo<<<dim3(8, 32), 256, SSMEM_BYTES>>>(vecbp, wob, dec, h0);
    // h1 = LN(h0) -> hi/lo planes + fp16 plane
    ln_kernel<<<MTOK, 256>>>(h0, g1, b1, h1h, h1l, h1f);
    // f0 = h1 + h1 @ Wff^T (fp16 single-plane MMA; exact hi/lo residual)
    gemm_ff16<<<dim3(8, 32), 256, SSMEM_BYTES>>>(h1f, wff16, h1h, h1l, f0);
    // out = 2*LN(f0) + pe[b]
    ln_final_kernel<<<MTOK, 256>>>(f0, g2, b2, out);
}